// round 7
// baseline (speedup 1.0000x reference)
#include <cuda_runtime.h>
#include <cuda_bf16.h>
#include <cstdint>

#define BPAIRS 4096
#define NROWS  8192
#define DCOLS  256

#define TL 64                  // tile grid dim (8192/128)
#define NT 2080                // TL*(TL+1)/2
#define GRID 296               // persistent CTAs

#define SKB 272                // padded smem row stride bytes
#define TILEB (128 * SKB)      // 34816 B per operand tile
#define A_OFF 0
#define B0_OFF TILEB
#define B1_OFF (2 * TILEB)
#define SMEM_TOTAL (3 * TILEB) // 104448

#define QSCALE 256.0f          // int8 = round(256 * x), |x| <~ 0.35 for this data
// exp2 arg: (4*g_true - 4)*log2e, g_true = acc / 65536
#define C1 (4.0f / 65536.0f * 1.4426950408889634f)
#define C2 (4.0f * 1.4426950408889634f)

__device__ __align__(16) int8_t g_X[NROWS * DCOLS];
__device__ float g_align[BPAIRS];
__device__ float g_uni[GRID];
__device__ unsigned int g_done;

__device__ __forceinline__ uint32_t smem_u32(const void* p) {
    uint32_t a;
    asm("{ .reg .u64 t; cvta.to.shared.u64 t, %1; cvt.u32.u64 %0, t; }" : "=r"(a) : "l"(p));
    return a;
}
__device__ __forceinline__ void imma(int d[4], const uint32_t a[4], uint32_t b0, uint32_t b1) {
    asm volatile(
        "mma.sync.aligned.m16n8k32.row.col.s32.s8.s8.s32 "
        "{%0,%1,%2,%3}, {%4,%5,%6,%7}, {%8,%9}, {%0,%1,%2,%3};\n"
        : "+r"(d[0]), "+r"(d[1]), "+r"(d[2]), "+r"(d[3])
        : "r"(a[0]), "r"(a[1]), "r"(a[2]), "r"(a[3]), "r"(b0), "r"(b1));
}
__device__ __forceinline__ void ldsm4(uint32_t r[4], uint32_t addr) {
    asm volatile("ldmatrix.sync.aligned.m8n8.x4.shared.b16 {%0,%1,%2,%3}, [%4];"
                 : "=r"(r[0]), "=r"(r[1]), "=r"(r[2]), "=r"(r[3]) : "r"(addr));
}
__device__ __forceinline__ void cpasync16(uint32_t dst, const void* src) {
    asm volatile("cp.async.cg.shared.global [%0], [%1], 16;" :: "r"(dst), "l"(src));
}
__device__ __forceinline__ float ex2(float x) {
    float r;
    asm("ex2.approx.ftz.f32 %0, %1;" : "=f"(r) : "f"(x));
    return r;
}

// normalize (fp32), per-row align partial, emit int8 = round(256*x)
__global__ void k_norm(const float* __restrict__ A, const float* __restrict__ B) {
    int r = blockIdx.x;
    int t = threadIdx.x;           // 256 == DCOLS
    if (r == 0 && t == 0) g_done = 0u;
    float a = A[r * DCOLS + t];
    float b = B[r * DCOLS + t];
    float sa = a * a, sb = b * b;
    #pragma unroll
    for (int o = 16; o; o >>= 1) {
        sa += __shfl_xor_sync(0xffffffffu, sa, o);
        sb += __shfl_xor_sync(0xffffffffu, sb, o);
    }
    __shared__ float ssa[8], ssb[8], sdd[8];
    int wid = t >> 5, lane = t & 31;
    if (lane == 0) { ssa[wid] = sa; ssb[wid] = sb; }
    __syncthreads();
    float na = 0.f, nb = 0.f;
    #pragma unroll
    for (int i = 0; i < 8; i++) { na += ssa[i]; nb += ssb[i]; }
    na = fmaxf(sqrtf(na), 1e-12f);
    nb = fmaxf(sqrtf(nb), 1e-12f);
    float an = a / na, bn = b / nb;
    int qa = __float2int_rn(an * QSCALE);
    int qb = __float2int_rn(bn * QSCALE);
    qa = max(-127, min(127, qa));
    qb = max(-127, min(127, qb));
    g_X[r * DCOLS + t] = (int8_t)qa;
    g_X[(BPAIRS + r) * DCOLS + t] = (int8_t)qb;
    float d = an - bn;
    float dd = d * d;
    #pragma unroll
    for (int o = 16; o; o >>= 1) dd += __shfl_xor_sync(0xffffffffu, dd, o);
    if (lane == 0) sdd[wid] = dd;
    __syncthreads();
    if (t == 0) {
        float s = 0.f;
        #pragma unroll
        for (int i = 0; i < 8; i++) s += sdd[i];
        g_align[r] = s;
    }
}

// persistent int8 Gram: 296 CTAs, contiguous row-major tile ranges over the
// upper triangle. A resident per row; B double-buffered + prefetched.
__global__ __launch_bounds__(256, 2) void k_gram(float* __restrict__ out) {
    extern __shared__ __align__(128) char smem[];
    __shared__ float sred[16];
    __shared__ int sflag[1];
    uint32_t sb = smem_u32(smem);

    int tid = threadIdx.x;
    int wid = tid >> 5, lane = tid & 31;
    int wm = wid >> 1, wn = wid & 1;
    int m0 = wm * 32, n0 = wn * 64;
    int cta = blockIdx.x;

    int lo = (int)(((long long)cta * NT) / GRID);
    int hi = (int)(((long long)(cta + 1) * NT) / GRID);

    // decode lo -> (bi, bj)
    int bi = 0, rem = lo, rl = TL;
    while (rem >= rl) { rem -= rl; bi++; rl--; }
    int bj = bi + rem;

    // per-lane fragment offsets within a tile buffer
    uint32_t a_off = (uint32_t)((m0 + (lane & 15)) * SKB + ((lane >> 4) << 4));
    int bcol = (lane & 7) + ((lane >> 4) << 3);
    uint32_t b_off = (uint32_t)((n0 + bcol) * SKB + ((lane & 8) ? 16 : 0));

    // stage helpers: 2048 x 16B chunks, 16 threads per 256B row
    auto stage = [&](uint32_t dstoff, int row128) {
        const int8_t* g = &g_X[(size_t)row128 * 128 * DCOLS];
        #pragma unroll
        for (int i = 0; i < 8; i++) {
            int idx = tid + i * 256;
            int r = idx >> 4, u = idx & 15;
            cpasync16(sb + dstoff + r * SKB + u * 16, g + (size_t)r * DCOLS + u * 16);
        }
    };

    float srun = 0.0f;
    int buf = 0;

    stage(A_OFF, bi);
    stage(B0_OFF, bj);
    asm volatile("cp.async.commit_group;" ::: "memory");

    for (int t = lo; t < hi; t++) {
        int nbi = bi, nbj = bj + 1;
        if (nbj >= TL) { nbi = bi + 1; nbj = nbi; }
        bool has_next = (t + 1 < hi);
        bool rowchg = (nbi != bi);

        asm volatile("cp.async.wait_group 0;" ::: "memory");
        __syncthreads();

        if (has_next && !rowchg) {
            stage(buf ? B0_OFF : B1_OFF, nbj);
            asm volatile("cp.async.commit_group;" ::: "memory");
        }

        uint32_t abase = sb + A_OFF + a_off;
        uint32_t bbase = sb + (buf ? B1_OFF : B0_OFF) + b_off;

        int acc[2][8][4];
        #pragma unroll
        for (int mi = 0; mi < 2; mi++)
            #pragma unroll
            for (int ni = 0; ni < 8; ni++)
                #pragma unroll
                for (int e = 0; e < 4; e++) acc[mi][ni][e] = 0;

        #pragma unroll
        for (int ks = 0; ks < DCOLS / 32; ks++) {
            uint32_t a0[4], a1[4];
            ldsm4(a0, abase + ks * 32);
            ldsm4(a1, abase + 16 * SKB + ks * 32);
            #pragma unroll
            for (int nb = 0; nb < 4; nb++) {
                uint32_t bf[4];
                ldsm4(bf, bbase + nb * 16 * SKB + ks * 32);
                imma(acc[0][2 * nb + 0], a0, bf[0], bf[1]);
                imma(acc[0][2 * nb + 1], a0, bf[2], bf[3]);
                imma(acc[1][2 * nb + 0], a1, bf[0], bf[1]);
                imma(acc[1][2 * nb + 1], a1, bf[2], bf[3]);
            }
        }

        // epilogue: exp2(min(acc*C1 - C2, 0))
        float s = 0.0f;
        #pragma unroll
        for (int mi = 0; mi < 2; mi++)
            #pragma unroll
            for (int ni = 0; ni < 8; ni++)
                #pragma unroll
                for (int e = 0; e < 4; e++) {
                    float gv = __int2float_rn(acc[mi][ni][e]);
                    float tt = fminf(gv * C1 - C2, 0.0f);
                    s += ex2(tt);
                }
        srun += (bi == bj) ? s : 2.0f * s;

        if (has_next && rowchg) {
            __syncthreads();
            stage(A_OFF, nbi);
            stage(buf ? B0_OFF : B1_OFF, nbj);
            asm volatile("cp.async.commit_group;" ::: "memory");
        }
        bi = nbi; bj = nbj; buf ^= 1;
    }

    // per-CTA reduction -> g_uni[cta]
    #pragma unroll
    for (int o = 16; o; o >>= 1) srun += __shfl_xor_sync(0xffffffffu, srun, o);
    if (lane == 0) sred[wid] = srun;
    __syncthreads();
    if (tid == 0) {
        float tot = 0.f;
        #pragma unroll
        for (int i = 0; i < 8; i++) tot += sred[i];
        g_uni[cta] = tot;
        __threadfence();
        unsigned int prev = atomicAdd(&g_done, 1u);
        sflag[0] = (prev == GRID - 1) ? 1 : 0;
    }
    __syncthreads();

    // last CTA finalizes
    if (sflag[0]) {
        float sa = 0.f, su = 0.f;
        for (int i = tid; i < BPAIRS; i += 256) sa += g_align[i];
        for (int i = tid; i < GRID; i += 256) su += g_uni[i];
        #pragma unroll
        for (int o = 16; o; o >>= 1) {
            sa += __shfl_xor_sync(0xffffffffu, sa, o);
            su += __shfl_xor_sync(0xffffffffu, su, o);
        }
        if (lane == 0) { sred[wid] = sa; sred[wid + 8] = su; }
        __syncthreads();
        if (tid == 0) {
            float ta = 0.f, tu = 0.f;
            #pragma unroll
            for (int i = 0; i < 8; i++) { ta += sred[i]; tu += sred[i + 8]; }
            float align_loss = ta / (float)BPAIRS;
            float uniform_loss = (tu - (float)NROWS) / ((float)NROWS * (float)(NROWS - 1));
            out[0] = align_loss + uniform_loss;
        }
    }
}

extern "C" void kernel_launch(void* const* d_in, const int* in_sizes, int n_in,
                              void* d_out, int out_size) {
    const float* A = (const float*)d_in[0];
    const float* B = (const float*)d_in[1];
    float* out = (float*)d_out;

    cudaFuncSetAttribute(k_gram, cudaFuncAttributeMaxDynamicSharedMemorySize, SMEM_TOTAL);

    k_norm<<<BPAIRS, 256>>>(A, B);
    k_gram<<<GRID, 256, SMEM_TOTAL>>>(out);
}

// round 8
// speedup vs baseline: 2.0998x; 2.0998x over previous
#include <cuda_runtime.h>
#include <cuda_fp16.h>
#include <cuda_fp8.h>
#include <cstdint>

#define BPAIRS 4096
#define NROWS  8192
#define DCOLS  256

#define TL 64
#define NT 2080                 // TL*(TL+1)/2 blocks

#define SKB 272                 // padded smem row stride bytes
#define TILEB (128 * SKB)       // 34816 B per operand
#define SMEM_TOTAL (2 * TILEB)  // 69632

#define QSCALE 16.0f            // g_fp8accum = 256 * g_true
// exp2 arg: (4*g_true - 4)*log2e = acc*C1 - C2
#define C1 (4.0f / 256.0f * 1.4426950408889634f)
#define C2 (4.0f * 1.4426950408889634f)

__device__ __align__(16) uint8_t g_X[NROWS * DCOLS];   // e4m3, scaled by 16
__device__ float g_align[BPAIRS];
__device__ float g_uni;
__device__ unsigned int g_done;

__device__ __forceinline__ uint32_t smem_u32(const void* p) {
    uint32_t a;
    asm("{ .reg .u64 t; cvta.to.shared.u64 t, %1; cvt.u32.u64 %0, t; }" : "=r"(a) : "l"(p));
    return a;
}
// fp8 MMA with f16 accumulator: D,C = 2 regs of f16x2
__device__ __forceinline__ void qmma_h(uint32_t d[2], const uint32_t a[4], uint32_t b0, uint32_t b1) {
    asm volatile(
        "mma.sync.aligned.m16n8k32.row.col.f16.e4m3.e4m3.f16 "
        "{%0,%1}, {%2,%3,%4,%5}, {%6,%7}, {%0,%1};\n"
        : "+r"(d[0]), "+r"(d[1])
        : "r"(a[0]), "r"(a[1]), "r"(a[2]), "r"(a[3]), "r"(b0), "r"(b1));
}
__device__ __forceinline__ void ldsm4(uint32_t r[4], uint32_t addr) {
    asm volatile("ldmatrix.sync.aligned.m8n8.x4.shared.b16 {%0,%1,%2,%3}, [%4];"
                 : "=r"(r[0]), "=r"(r[1]), "=r"(r[2]), "=r"(r[3]) : "r"(addr));
}
__device__ __forceinline__ void cpasync16(uint32_t dst, const void* src) {
    asm volatile("cp.async.cg.shared.global [%0], [%1], 16;" :: "r"(dst), "l"(src));
}
__device__ __forceinline__ float ex2(float x) {
    float r;
    asm("ex2.approx.ftz.f32 %0, %1;" : "=f"(r) : "f"(x));
    return r;
}

// normalize (fp32), per-row align partial, emit e4m3 scaled by 16
__global__ void k_norm(const float* __restrict__ A, const float* __restrict__ B) {
    int r = blockIdx.x;
    int t = threadIdx.x;           // 256 == DCOLS
    if (r == 0 && t == 0) { g_done = 0u; g_uni = 0.0f; }
    float a = A[r * DCOLS + t];
    float b = B[r * DCOLS + t];
    float sa = a * a, sb = b * b;
    #pragma unroll
    for (int o = 16; o; o >>= 1) {
        sa += __shfl_xor_sync(0xffffffffu, sa, o);
        sb += __shfl_xor_sync(0xffffffffu, sb, o);
    }
    __shared__ float ssa[8], ssb[8], sdd[8];
    int wid = t >> 5, lane = t & 31;
    if (lane == 0) { ssa[wid] = sa; ssb[wid] = sb; }
    __syncthreads();
    float na = 0.f, nb = 0.f;
    #pragma unroll
    for (int i = 0; i < 8; i++) { na += ssa[i]; nb += ssb[i]; }
    na = fmaxf(sqrtf(na), 1e-12f);
    nb = fmaxf(sqrtf(nb), 1e-12f);
    float an = a / na, bn = b / nb;
    g_X[r * DCOLS + t] =
        (uint8_t)__nv_cvt_float_to_fp8(an * QSCALE, __NV_SATFINITE, __NV_E4M3);
    g_X[(BPAIRS + r) * DCOLS + t] =
        (uint8_t)__nv_cvt_float_to_fp8(bn * QSCALE, __NV_SATFINITE, __NV_E4M3);
    float d = an - bn;
    float dd = d * d;
    #pragma unroll
    for (int o = 16; o; o >>= 1) dd += __shfl_xor_sync(0xffffffffu, dd, o);
    if (lane == 0) sdd[wid] = dd;
    __syncthreads();
    if (t == 0) {
        float s = 0.f;
        #pragma unroll
        for (int i = 0; i < 8; i++) s += sdd[i];
        g_align[r] = s;
    }
}

// fp8 Gram, f16 accum. One block per upper-triangular 128x128 tile.
__global__ __launch_bounds__(256, 2) void k_gram(float* __restrict__ out) {
    extern __shared__ __align__(128) char smem[];
    __shared__ float sred[16];
    __shared__ int sflag[1];
    uint32_t sb = smem_u32(smem);

    int tid = threadIdx.x;
    int wid = tid >> 5, lane = tid & 31;
    int wm = wid >> 1, wn = wid & 1;
    int m0 = wm * 32, n0 = wn * 64;

    // decode (bi, bj), bj >= bi
    int bi = 0, rem = blockIdx.x, rl = TL;
    while (rem >= rl) { rem -= rl; bi++; rl--; }
    int bj = bi + rem;
    int ai0 = bi * 128, bj0 = bj * 128;

    // stage A and B tiles (full K=256): 2048 x 16B chunks each
    {
        const uint8_t* ga = &g_X[(size_t)ai0 * DCOLS];
        const uint8_t* gb = &g_X[(size_t)bj0 * DCOLS];
        #pragma unroll
        for (int i = 0; i < 8; i++) {
            int idx = tid + i * 256;
            int r = idx >> 4, u = idx & 15;
            cpasync16(sb + r * SKB + u * 16, ga + (size_t)r * DCOLS + u * 16);
            cpasync16(sb + TILEB + r * SKB + u * 16, gb + (size_t)r * DCOLS + u * 16);
        }
        asm volatile("cp.async.commit_group;" ::: "memory");
        asm volatile("cp.async.wait_group 0;" ::: "memory");
    }
    __syncthreads();

    uint32_t a_off = (uint32_t)((m0 + (lane & 15)) * SKB + ((lane >> 4) << 4));
    int bcol = (lane & 7) + ((lane >> 4) << 3);
    uint32_t b_off = (uint32_t)((n0 + bcol) * SKB + ((lane & 8) ? 16 : 0));

    uint32_t acc[2][8][2];
    #pragma unroll
    for (int mi = 0; mi < 2; mi++)
        #pragma unroll
        for (int ni = 0; ni < 8; ni++) { acc[mi][ni][0] = 0u; acc[mi][ni][1] = 0u; }

    uint32_t abase = sb + a_off;
    uint32_t bbase = sb + TILEB + b_off;

    #pragma unroll
    for (int ks = 0; ks < DCOLS / 32; ks++) {
        uint32_t a0[4], a1[4];
        ldsm4(a0, abase + ks * 32);
        ldsm4(a1, abase + 16 * SKB + ks * 32);
        #pragma unroll
        for (int nb = 0; nb < 4; nb++) {
            uint32_t bf[4];
            ldsm4(bf, bbase + nb * 16 * SKB + ks * 32);
            qmma_h(acc[0][2 * nb + 0], a0, bf[0], bf[1]);
            qmma_h(acc[0][2 * nb + 1], a0, bf[2], bf[3]);
            qmma_h(acc[1][2 * nb + 0], a1, bf[0], bf[1]);
            qmma_h(acc[1][2 * nb + 1], a1, bf[2], bf[3]);
        }
    }

    // epilogue: unpack f16x2, exp2(min(acc*C1 - C2, 0))
    float s = 0.0f;
    #pragma unroll
    for (int mi = 0; mi < 2; mi++)
        #pragma unroll
        for (int ni = 0; ni < 8; ni++)
            #pragma unroll
            for (int e = 0; e < 2; e++) {
                __half2 h2 = *reinterpret_cast<__half2*>(&acc[mi][ni][e]);
                float2 f = __half22float2(h2);
                s += ex2(fminf(f.x * C1 - C2, 0.0f));
                s += ex2(fminf(f.y * C1 - C2, 0.0f));
            }
    if (bi != bj) s *= 2.0f;
    #pragma unroll
    for (int o = 16; o; o >>= 1) s += __shfl_xor_sync(0xffffffffu, s, o);
    if (lane == 0) sred[wid] = s;
    __syncthreads();
    if (tid == 0) {
        float tot = 0.f;
        #pragma unroll
        for (int i = 0; i < 8; i++) tot += sred[i];
        atomicAdd(&g_uni, tot);
        __threadfence();
        unsigned int prev = atomicAdd(&g_done, 1u);
        sflag[0] = (prev == NT - 1) ? 1 : 0;
    }
    __syncthreads();

    // last block finalizes
    if (sflag[0]) {
        float sa = 0.f;
        for (int i = tid; i < BPAIRS; i += 256) sa += g_align[i];
        #pragma unroll
        for (int o = 16; o; o >>= 1) sa += __shfl_xor_sync(0xffffffffu, sa, o);
        if (lane == 0) sred[wid] = sa;
        __syncthreads();
        if (tid == 0) {
            float ta = 0.f;
            #pragma unroll
            for (int i = 0; i < 8; i++) ta += sred[i];
            float align_loss = ta / (float)BPAIRS;
            float uniform_loss = (g_uni - (float)NROWS) / ((float)NROWS * (float)(NROWS - 1));
            out[0] = align_loss + uniform_loss;
        }
    }
}

extern "C" void kernel_launch(void* const* d_in, const int* in_sizes, int n_in,
                              void* d_out, int out_size) {
    const float* A = (const float*)d_in[0];
    const float* B = (const float*)d_in[1];
    float* out = (float*)d_out;

    cudaFuncSetAttribute(k_gram, cudaFuncAttributeMaxDynamicSharedMemorySize, SMEM_TOTAL);

    k_norm<<<BPAIRS, 256>>>(A, B);
    k_gram<<<NT, 256, SMEM_TOTAL>>>(out);
}

// round 9
// speedup vs baseline: 2.1792x; 1.0378x over previous
#include <cuda_runtime.h>
#include <cuda_bf16.h>
#include <cstdint>

#define BPAIRS 4096
#define NROWS  8192
#define DCOLS  256

#define TL 64
#define NT 2080                // TL*(TL+1)/2 blocks

// gram tiling (R2-proven): bf16, K chunks of 64, double-buffered
#define KC 64
#define NCHUNK (DCOLS / KC)    // 4
#define SK  72                 // padded smem stride (bf16)
#define SKB 144                // stride bytes
#define TILEB (128 * SKB)      // 18432 B per operand buffer
#define SMEM_TOTAL (4 * TILEB) // A0 B0 A1 B1 = 73728

__device__ __align__(16) __nv_bfloat16 g_X[NROWS * DCOLS];
__device__ float g_align[BPAIRS];
__device__ float g_uni;
__device__ unsigned int g_done;

__device__ __forceinline__ uint32_t smem_u32(const void* p) {
    uint32_t a;
    asm("{ .reg .u64 t; cvta.to.shared.u64 t, %1; cvt.u32.u64 %0, t; }" : "=r"(a) : "l"(p));
    return a;
}
__device__ __forceinline__ void mma16816(float d[4], const uint32_t a[4], uint32_t b0, uint32_t b1) {
    asm volatile(
        "mma.sync.aligned.m16n8k16.row.col.f32.bf16.bf16.f32 "
        "{%0,%1,%2,%3}, {%4,%5,%6,%7}, {%8,%9}, {%0,%1,%2,%3};\n"
        : "+f"(d[0]), "+f"(d[1]), "+f"(d[2]), "+f"(d[3])
        : "r"(a[0]), "r"(a[1]), "r"(a[2]), "r"(a[3]), "r"(b0), "r"(b1));
}
__device__ __forceinline__ void ldsm4(uint32_t r[4], uint32_t addr) {
    asm volatile("ldmatrix.sync.aligned.m8n8.x4.shared.b16 {%0,%1,%2,%3}, [%4];"
                 : "=r"(r[0]), "=r"(r[1]), "=r"(r[2]), "=r"(r[3]) : "r"(addr));
}
__device__ __forceinline__ void cpasync16(uint32_t dst, const void* src) {
    asm volatile("cp.async.cg.shared.global [%0], [%1], 16;" :: "r"(dst), "l"(src));
}
__device__ __forceinline__ float ex2(float x) {
    float r;
    asm("ex2.approx.ftz.f32 %0, %1;" : "=f"(r) : "f"(x));
    return r;
}

// exp2 arg: (4g - 4) * log2e
#define C1f (4.0f * 1.4426950408889634f)
#define C2f (4.0f * 1.4426950408889634f)

// normalize (fp32), per-row align partial, emit bf16; init counters
__global__ void k_norm(const float* __restrict__ A, const float* __restrict__ B) {
    int r = blockIdx.x;
    int t = threadIdx.x;           // 256 == DCOLS
    if (r == 0 && t == 0) { g_done = 0u; g_uni = 0.0f; }
    float a = A[r * DCOLS + t];
    float b = B[r * DCOLS + t];
    float sa = a * a, sb = b * b;
    #pragma unroll
    for (int o = 16; o; o >>= 1) {
        sa += __shfl_xor_sync(0xffffffffu, sa, o);
        sb += __shfl_xor_sync(0xffffffffu, sb, o);
    }
    __shared__ float ssa[8], ssb[8], sdd[8];
    int wid = t >> 5, lane = t & 31;
    if (lane == 0) { ssa[wid] = sa; ssb[wid] = sb; }
    __syncthreads();
    float na = 0.f, nb = 0.f;
    #pragma unroll
    for (int i = 0; i < 8; i++) { na += ssa[i]; nb += ssb[i]; }
    na = fmaxf(sqrtf(na), 1e-12f);
    nb = fmaxf(sqrtf(nb), 1e-12f);
    float an = a / na, bn = b / nb;
    g_X[r * DCOLS + t] = __float2bfloat16(an);
    g_X[(BPAIRS + r) * DCOLS + t] = __float2bfloat16(bn);
    float d = an - bn;
    float dd = d * d;
    #pragma unroll
    for (int o = 16; o; o >>= 1) dd += __shfl_xor_sync(0xffffffffu, dd, o);
    if (lane == 0) sdd[wid] = dd;
    __syncthreads();
    if (t == 0) {
        float s = 0.f;
        #pragma unroll
        for (int i = 0; i < 8; i++) s += sdd[i];
        g_align[r] = s;
    }
}

// bf16 Gram (R2 structure) over upper-triangular 128x128 tiles,
// fused exp epilogue + done-counter finalize.
__global__ __launch_bounds__(256, 2) void k_gram(float* __restrict__ out) {
    extern __shared__ __align__(128) char smem[];
    __shared__ float sred[8];
    __shared__ int sflag[1];
    uint32_t sb = smem_u32(smem);

    int tid = threadIdx.x;
    int wid = tid >> 5, lane = tid & 31;
    int wm = wid >> 1, wn = wid & 1;
    int m0 = wm * 32, n0 = wn * 64;

    // decode (bi, bj), bj >= bi
    int bi = 0, rem = blockIdx.x, rl = TL;
    while (rem >= rl) { rem -= rl; bi++; rl--; }
    int bj = bi + rem;
    int ai0 = bi * 128, bj0 = bj * 128;

    // fragment base offsets
    uint32_t a_off = (uint32_t)((m0 + (lane & 15)) * SKB + ((lane >> 4) << 4));
    int bcol = (lane & 7) + ((lane >> 4) << 3);
    uint32_t b_off = (uint32_t)((n0 + bcol) * SKB + ((lane & 8) ? 16 : 0));

    float acc[2][8][4];
    #pragma unroll
    for (int mi = 0; mi < 2; mi++)
        #pragma unroll
        for (int ni = 0; ni < 8; ni++)
            #pragma unroll
            for (int e = 0; e < 4; e++) acc[mi][ni][e] = 0.0f;

    // prologue: stage chunks 0 and 1
    #pragma unroll
    for (int c = 0; c < 2; c++) {
        uint32_t ab = sb + (2 * c + 0) * TILEB;
        uint32_t bb = sb + (2 * c + 1) * TILEB;
        const __nv_bfloat16* ga = &g_X[(size_t)ai0 * DCOLS + c * KC];
        const __nv_bfloat16* gb = &g_X[(size_t)bj0 * DCOLS + c * KC];
        #pragma unroll
        for (int i = 0; i < 4; i++) {
            int idx = tid + i * 256;
            int r = idx >> 3, u = idx & 7;
            cpasync16(ab + r * SKB + u * 16, ga + (size_t)r * DCOLS + u * 8);
            cpasync16(bb + r * SKB + u * 16, gb + (size_t)r * DCOLS + u * 8);
        }
        asm volatile("cp.async.commit_group;" ::: "memory");
    }

    #pragma unroll
    for (int c = 0; c < NCHUNK; c++) {
        if (c == 3) asm volatile("cp.async.wait_group 0;" ::: "memory");
        else        asm volatile("cp.async.wait_group 1;" ::: "memory");
        __syncthreads();

        uint32_t abase = sb + (2 * (c & 1) + 0) * TILEB + a_off;
        uint32_t bbase = sb + (2 * (c & 1) + 1) * TILEB + b_off;

        #pragma unroll
        for (int ks = 0; ks < KC / 16; ks++) {
            uint32_t a0[4], a1[4];
            ldsm4(a0, abase + ks * 32);
            ldsm4(a1, abase + 16 * SKB + ks * 32);
            #pragma unroll
            for (int nb = 0; nb < 4; nb++) {
                uint32_t bf[4];
                ldsm4(bf, bbase + nb * 16 * SKB + ks * 32);
                mma16816(acc[0][2 * nb + 0], a0, bf[0], bf[1]);
                mma16816(acc[0][2 * nb + 1], a0, bf[2], bf[3]);
                mma16816(acc[1][2 * nb + 0], a1, bf[0], bf[1]);
                mma16816(acc[1][2 * nb + 1], a1, bf[2], bf[3]);
            }
        }
        __syncthreads();

        if (c < 2) {
            int cn = c + 2;
            uint32_t ab = sb + (2 * (cn & 1) + 0) * TILEB;
            uint32_t bb = sb + (2 * (cn & 1) + 1) * TILEB;
            const __nv_bfloat16* ga = &g_X[(size_t)ai0 * DCOLS + cn * KC];
            const __nv_bfloat16* gb = &g_X[(size_t)bj0 * DCOLS + cn * KC];
            #pragma unroll
            for (int i = 0; i < 4; i++) {
                int idx = tid + i * 256;
                int r = idx >> 3, u = idx & 7;
                cpasync16(ab + r * SKB + u * 16, ga + (size_t)r * DCOLS + u * 8);
                cpasync16(bb + r * SKB + u * 16, gb + (size_t)r * DCOLS + u * 8);
            }
            asm volatile("cp.async.commit_group;" ::: "memory");
        }
    }

    // epilogue: exp2(min((4g-4)*log2e, 0))
    float s = 0.0f;
    #pragma unroll
    for (int mi = 0; mi < 2; mi++)
        #pragma unroll
        for (int ni = 0; ni < 8; ni++)
            #pragma unroll
            for (int e = 0; e < 4; e++) {
                float tt = fminf(acc[mi][ni][e] * C1f - C2f, 0.0f);
                s += ex2(tt);
            }
    if (bi != bj) s *= 2.0f;
    #pragma unroll
    for (int o = 16; o; o >>= 1) s += __shfl_xor_sync(0xffffffffu, s, o);
    if (lane == 0) sred[wid] = s;
    __syncthreads();
    if (tid == 0) {
        float tot = 0.f;
        #pragma unroll
        for (int i = 0; i < 8; i++) tot += sred[i];
        atomicAdd(&g_uni, tot);
        __threadfence();
        unsigned int prev = atomicAdd(&g_done, 1u);
        sflag[0] = (prev == NT - 1) ? 1 : 0;
    }
    __syncthreads();

    // last block finalizes
    if (sflag[0]) {
        float sa = 0.f;
        for (int i = tid; i < BPAIRS; i += 256) sa += g_align[i];
        #pragma unroll
        for (int o = 16; o; o >>= 1) sa += __shfl_xor_sync(0xffffffffu, sa, o);
        if (lane == 0) sred[wid] = sa;
        __syncthreads();
        if (tid == 0) {
            float ta = 0.f;
            #pragma unroll
            for (int i = 0; i < 8; i++) ta += sred[i];
            float align_loss = ta / (float)BPAIRS;
            float uni = *(volatile float*)&g_uni;
            float uniform_loss = (uni - (float)NROWS) / ((float)NROWS * (float)(NROWS - 1));
            out[0] = align_loss + uniform_loss;
        }
    }
}

extern "C" void kernel_launch(void* const* d_in, const int* in_sizes, int n_in,
                              void* d_out, int out_size) {
    const float* A = (const float*)d_in[0];
    const float* B = (const float*)d_in[1];
    float* out = (float*)d_out;

    cudaFuncSetAttribute(k_gram, cudaFuncAttributeMaxDynamicSharedMemorySize, SMEM_TOTAL);

    k_norm<<<BPAIRS, 256>>>(A, B);
    k_gram<<<NT, 256, SMEM_TOTAL>>>(out);
}

// round 10
// speedup vs baseline: 2.2320x; 1.0242x over previous
#include <cuda_runtime.h>
#include <cuda_bf16.h>
#include <cstdint>

#define BPAIRS 4096
#define NROWS  8192
#define DCOLS  256

#define TL 64
#define NT 2080                // TL*(TL+1)/2 blocks

// bf16 gram tiling: K chunks of 64, ring-of-3 buffers
#define KC 64
#define NCHUNK (DCOLS / KC)    // 4
#define SKB 144                // padded stride bytes (72 bf16)
#define TILEB (128 * SKB)      // 18432 B per operand buffer
#define SMEM_TOTAL (6 * TILEB) // A0 B0 A1 B1 A2 B2 = 110592

__device__ __align__(16) __nv_bfloat16 g_X[NROWS * DCOLS];
__device__ float g_align[BPAIRS];
__device__ float g_uni;
__device__ unsigned int g_done;

__device__ __forceinline__ uint32_t smem_u32(const void* p) {
    uint32_t a;
    asm("{ .reg .u64 t; cvta.to.shared.u64 t, %1; cvt.u32.u64 %0, t; }" : "=r"(a) : "l"(p));
    return a;
}
__device__ __forceinline__ void mma16816(float d[4], const uint32_t a[4], uint32_t b0, uint32_t b1) {
    asm volatile(
        "mma.sync.aligned.m16n8k16.row.col.f32.bf16.bf16.f32 "
        "{%0,%1,%2,%3}, {%4,%5,%6,%7}, {%8,%9}, {%0,%1,%2,%3};\n"
        : "+f"(d[0]), "+f"(d[1]), "+f"(d[2]), "+f"(d[3])
        : "r"(a[0]), "r"(a[1]), "r"(a[2]), "r"(a[3]), "r"(b0), "r"(b1));
}
__device__ __forceinline__ void ldsm4(uint32_t r[4], uint32_t addr) {
    asm volatile("ldmatrix.sync.aligned.m8n8.x4.shared.b16 {%0,%1,%2,%3}, [%4];"
                 : "=r"(r[0]), "=r"(r[1]), "=r"(r[2]), "=r"(r[3]) : "r"(addr));
}
__device__ __forceinline__ void cpasync16(uint32_t dst, const void* src) {
    asm volatile("cp.async.cg.shared.global [%0], [%1], 16;" :: "r"(dst), "l"(src));
}
__device__ __forceinline__ float ex2(float x) {
    float r;
    asm("ex2.approx.ftz.f32 %0, %1;" : "=f"(r) : "f"(x));
    return r;
}

#define C1f (4.0f * 1.4426950408889634f)
#define C2f (4.0f * 1.4426950408889634f)

// normalize (fp32), per-row align partial, emit bf16; init counters
__global__ void k_norm(const float* __restrict__ A, const float* __restrict__ B) {
    int r = blockIdx.x;
    int t = threadIdx.x;           // 256 == DCOLS
    if (r == 0 && t == 0) { g_done = 0u; g_uni = 0.0f; }
    float a = A[r * DCOLS + t];
    float b = B[r * DCOLS + t];
    float sa = a * a, sb = b * b;
    #pragma unroll
    for (int o = 16; o; o >>= 1) {
        sa += __shfl_xor_sync(0xffffffffu, sa, o);
        sb += __shfl_xor_sync(0xffffffffu, sb, o);
    }
    __shared__ float ssa[8], ssb[8], sdd[8];
    int wid = t >> 5, lane = t & 31;
    if (lane == 0) { ssa[wid] = sa; ssb[wid] = sb; }
    __syncthreads();
    float na = 0.f, nb = 0.f;
    #pragma unroll
    for (int i = 0; i < 8; i++) { na += ssa[i]; nb += ssb[i]; }
    na = fmaxf(sqrtf(na), 1e-12f);
    nb = fmaxf(sqrtf(nb), 1e-12f);
    float an = a / na, bn = b / nb;
    g_X[r * DCOLS + t] = __float2bfloat16(an);
    g_X[(BPAIRS + r) * DCOLS + t] = __float2bfloat16(bn);
    float d = an - bn;
    float dd = d * d;
    #pragma unroll
    for (int o = 16; o; o >>= 1) dd += __shfl_xor_sync(0xffffffffu, dd, o);
    if (lane == 0) sdd[wid] = dd;
    __syncthreads();
    if (t == 0) {
        float s = 0.f;
        #pragma unroll
        for (int i = 0; i < 8; i++) s += sdd[i];
        g_align[r] = s;
    }
}

// bf16 Gram, ring-of-3 K-chunk buffers, one barrier per chunk,
// staging issued before compute. Fused exp epilogue + finalize.
__global__ __launch_bounds__(256, 2) void k_gram(float* __restrict__ out) {
    extern __shared__ __align__(128) char smem[];
    __shared__ float sred[8];
    __shared__ int sflag[1];
    uint32_t sb = smem_u32(smem);

    int tid = threadIdx.x;
    int wid = tid >> 5, lane = tid & 31;
    int wm = wid >> 1, wn = wid & 1;
    int m0 = wm * 32, n0 = wn * 64;

    // decode (bi, bj), bj >= bi
    int bi = 0, rem = blockIdx.x, rl = TL;
    while (rem >= rl) { rem -= rl; bi++; rl--; }
    int bj = bi + rem;
    int ai0 = bi * 128, bj0 = bj * 128;

    // fragment base offsets
    uint32_t a_off = (uint32_t)((m0 + (lane & 15)) * SKB + ((lane >> 4) << 4));
    int bcol = (lane & 7) + ((lane >> 4) << 3);
    uint32_t b_off = (uint32_t)((n0 + bcol) * SKB + ((lane & 8) ? 16 : 0));

    // staging coords: 8 threads per 128B chunk-row
    int sr = tid >> 3, su = tid & 7;   // used with stride 32 rows per step

    // stage chunk c into ring slot (c % 3)
    auto stage = [&](int c) {
        int slot = c % 3;
        uint32_t ab = sb + (2 * slot + 0) * TILEB;
        uint32_t bb = sb + (2 * slot + 1) * TILEB;
        const __nv_bfloat16* ga = &g_X[(size_t)ai0 * DCOLS + c * KC];
        const __nv_bfloat16* gb = &g_X[(size_t)bj0 * DCOLS + c * KC];
        #pragma unroll
        for (int i = 0; i < 4; i++) {
            int r = sr + i * 32;
            cpasync16(ab + r * SKB + su * 16, ga + (size_t)r * DCOLS + su * 8);
            cpasync16(bb + r * SKB + su * 16, gb + (size_t)r * DCOLS + su * 8);
        }
        asm volatile("cp.async.commit_group;" ::: "memory");
    };

    float acc[2][8][4];
    #pragma unroll
    for (int mi = 0; mi < 2; mi++)
        #pragma unroll
        for (int ni = 0; ni < 8; ni++)
            #pragma unroll
            for (int e = 0; e < 4; e++) acc[mi][ni][e] = 0.0f;

    // prologue: chunks 0, 1
    stage(0);
    stage(1);

    #pragma unroll
    for (int c = 0; c < NCHUNK; c++) {
        // arrival of chunk c: allow 1 outstanding group (chunk c+1) except last
        if (c == NCHUNK - 1) asm volatile("cp.async.wait_group 0;" ::: "memory");
        else                 asm volatile("cp.async.wait_group 1;" ::: "memory");
        __syncthreads();   // also guarantees all warps done computing chunk c-1

        // stage chunk c+2 into slot (c+2)%3 == slot of chunk c-1 (now free)
        if (c + 2 < NCHUNK) stage(c + 2);

        int slot = c % 3;
        uint32_t abase = sb + (2 * slot + 0) * TILEB + a_off;
        uint32_t bbase = sb + (2 * slot + 1) * TILEB + b_off;

        #pragma unroll
        for (int ks = 0; ks < KC / 16; ks++) {
            uint32_t a0[4], a1[4];
            ldsm4(a0, abase + ks * 32);
            ldsm4(a1, abase + 16 * SKB + ks * 32);
            #pragma unroll
            for (int nb = 0; nb < 4; nb++) {
                uint32_t bf[4];
                ldsm4(bf, bbase + nb * 16 * SKB + ks * 32);
                mma16816(acc[0][2 * nb + 0], a0, bf[0], bf[1]);
                mma16816(acc[0][2 * nb + 1], a0, bf[2], bf[3]);
                mma16816(acc[1][2 * nb + 0], a1, bf[0], bf[1]);
                mma16816(acc[1][2 * nb + 1], a1, bf[2], bf[3]);
            }
        }
    }

    // epilogue: exp2(min((4g-4)*log2e, 0))
    float s = 0.0f;
    #pragma unroll
    for (int mi = 0; mi < 2; mi++)
        #pragma unroll
        for (int ni = 0; ni < 8; ni++)
            #pragma unroll
            for (int e = 0; e < 4; e++) {
                float tt = fminf(acc[mi][ni][e] * C1f - C2f, 0.0f);
                s += ex2(tt);
            }
    if (bi != bj) s *= 2.0f;
    #pragma unroll
    for (int o = 16; o; o >>= 1) s += __shfl_xor_sync(0xffffffffu, s, o);
    if (lane == 0) sred[wid] = s;
    __syncthreads();
    if (tid == 0) {
        float tot = 0.f;
        #pragma unroll
        for (int i = 0; i < 8; i++) tot += sred[i];
        atomicAdd(&g_uni, tot);
        __threadfence();
        unsigned int prev = atomicAdd(&g_done, 1u);
        sflag[0] = (prev == NT - 1) ? 1 : 0;
    }
    __syncthreads();

    // last block finalizes
    if (sflag[0]) {
        float sa = 0.f;
        for (int i = tid; i < BPAIRS; i += 256) sa += g_align[i];
        #pragma unroll
        for (int o = 16; o; o >>= 1) sa += __shfl_xor_sync(0xffffffffu, sa, o);
        if (lane == 0) sred[wid] = sa;
        __syncthreads();
        if (tid == 0) {
            float ta = 0.f;
            #pragma unroll
            for (int i = 0; i < 8; i++) ta += sred[i];
            float align_loss = ta / (float)BPAIRS;
            float uni = *(volatile float*)&g_uni;
            float uniform_loss = (uni - (float)NROWS) / ((float)NROWS * (float)(NROWS - 1));
            out[0] = align_loss + uniform_loss;
        }
    }
}

extern "C" void kernel_launch(void* const* d_in, const int* in_sizes, int n_in,
                              void* d_out, int out_size) {
    const float* A = (const float*)d_in[0];
    const float* B = (const float*)d_in[1];
    float* out = (float*)d_out;

    cudaFuncSetAttribute(k_gram, cudaFuncAttributeMaxDynamicSharedMemorySize, SMEM_TOTAL);

    k_norm<<<BPAIRS, 256>>>(A, B);
    k_gram<<<NT, 256, SMEM_TOTAL>>>(out);
}

// round 11
// speedup vs baseline: 2.2396x; 1.0034x over previous
#include <cuda_runtime.h>
#include <cuda_bf16.h>
#include <cstdint>

#define BPAIRS 4096
#define NROWS  8192
#define DCOLS  256

#define TL 64
#define NT 2080                // TL*(TL+1)/2 blocks
#define NTHR 512               // 16 warps per CTA

// bf16 gram tiling: K chunks of 64, ring-of-3 buffers
#define KC 64
#define NCHUNK (DCOLS / KC)    // 4
#define SKB 144                // padded stride bytes (72 bf16)
#define TILEB (128 * SKB)      // 18432 B per operand buffer
#define SMEM_TOTAL (6 * TILEB) // 110592; x2 CTAs = 221184 <= 228KB

__device__ __align__(16) __nv_bfloat16 g_X[NROWS * DCOLS];
__device__ float g_align[BPAIRS];
__device__ float g_uni;
__device__ unsigned int g_done;

__device__ __forceinline__ uint32_t smem_u32(const void* p) {
    uint32_t a;
    asm("{ .reg .u64 t; cvta.to.shared.u64 t, %1; cvt.u32.u64 %0, t; }" : "=r"(a) : "l"(p));
    return a;
}
__device__ __forceinline__ void mma16816(float d[4], const uint32_t a[4], uint32_t b0, uint32_t b1) {
    asm volatile(
        "mma.sync.aligned.m16n8k16.row.col.f32.bf16.bf16.f32 "
        "{%0,%1,%2,%3}, {%4,%5,%6,%7}, {%8,%9}, {%0,%1,%2,%3};\n"
        : "+f"(d[0]), "+f"(d[1]), "+f"(d[2]), "+f"(d[3])
        : "r"(a[0]), "r"(a[1]), "r"(a[2]), "r"(a[3]), "r"(b0), "r"(b1));
}
__device__ __forceinline__ void ldsm4(uint32_t r[4], uint32_t addr) {
    asm volatile("ldmatrix.sync.aligned.m8n8.x4.shared.b16 {%0,%1,%2,%3}, [%4];"
                 : "=r"(r[0]), "=r"(r[1]), "=r"(r[2]), "=r"(r[3]) : "r"(addr));
}
__device__ __forceinline__ void cpasync16(uint32_t dst, const void* src) {
    asm volatile("cp.async.cg.shared.global [%0], [%1], 16;" :: "r"(dst), "l"(src));
}
__device__ __forceinline__ float ex2(float x) {
    float r;
    asm("ex2.approx.ftz.f32 %0, %1;" : "=f"(r) : "f"(x));
    return r;
}

#define C1f (4.0f * 1.4426950408889634f)
#define C2f (4.0f * 1.4426950408889634f)

// normalize (fp32), per-row align partial, emit bf16; init counters
__global__ void k_norm(const float* __restrict__ A, const float* __restrict__ B) {
    int r = blockIdx.x;
    int t = threadIdx.x;           // 256 == DCOLS
    if (r == 0 && t == 0) { g_done = 0u; g_uni = 0.0f; }
    float a = A[r * DCOLS + t];
    float b = B[r * DCOLS + t];
    float sa = a * a, sb = b * b;
    #pragma unroll
    for (int o = 16; o; o >>= 1) {
        sa += __shfl_xor_sync(0xffffffffu, sa, o);
        sb += __shfl_xor_sync(0xffffffffu, sb, o);
    }
    __shared__ float ssa[8], ssb[8], sdd[8];
    int wid = t >> 5, lane = t & 31;
    if (lane == 0) { ssa[wid] = sa; ssb[wid] = sb; }
    __syncthreads();
    float na = 0.f, nb = 0.f;
    #pragma unroll
    for (int i = 0; i < 8; i++) { na += ssa[i]; nb += ssb[i]; }
    na = fmaxf(sqrtf(na), 1e-12f);
    nb = fmaxf(sqrtf(nb), 1e-12f);
    float an = a / na, bn = b / nb;
    g_X[r * DCOLS + t] = __float2bfloat16(an);
    g_X[(BPAIRS + r) * DCOLS + t] = __float2bfloat16(bn);
    float d = an - bn;
    float dd = d * d;
    #pragma unroll
    for (int o = 16; o; o >>= 1) dd += __shfl_xor_sync(0xffffffffu, dd, o);
    if (lane == 0) sdd[wid] = dd;
    __syncthreads();
    if (t == 0) {
        float s = 0.f;
        #pragma unroll
        for (int i = 0; i < 8; i++) s += sdd[i];
        g_align[r] = s;
    }
}

// bf16 Gram: 512-thread CTAs, 16 warps in a 4x4 grid of 32x32 warp tiles,
// ring-of-3 K-chunk buffers, one barrier per chunk. Fused exp + finalize.
__global__ __launch_bounds__(NTHR, 2) void k_gram(float* __restrict__ out) {
    extern __shared__ __align__(128) char smem[];
    __shared__ float sred[16];
    __shared__ int sflag[1];
    uint32_t sb = smem_u32(smem);

    int tid = threadIdx.x;
    int wid = tid >> 5, lane = tid & 31;
    int wm = wid >> 2, wn = wid & 3;       // 4x4 warp grid
    int m0 = wm * 32, n0 = wn * 32;

    // decode (bi, bj), bj >= bi
    int bi = 0, rem = blockIdx.x, rl = TL;
    while (rem >= rl) { rem -= rl; bi++; rl--; }
    int bj = bi + rem;
    int ai0 = bi * 128, bj0 = bj * 128;

    // fragment base offsets
    uint32_t a_off = (uint32_t)((m0 + (lane & 15)) * SKB + ((lane >> 4) << 4));
    int bcol = (lane & 7) + ((lane >> 4) << 3);
    uint32_t b_off = (uint32_t)((n0 + bcol) * SKB + ((lane & 8) ? 16 : 0));

    // staging coords: 8 threads per 128B chunk-row, 512 threads cover 64 rows
    int sr0 = tid >> 3, su = tid & 7;

    auto stage = [&](int c) {
        int slot = c % 3;
        uint32_t ab = sb + (2 * slot + 0) * TILEB;
        uint32_t bb = sb + (2 * slot + 1) * TILEB;
        const __nv_bfloat16* ga = &g_X[(size_t)ai0 * DCOLS + c * KC];
        const __nv_bfloat16* gb = &g_X[(size_t)bj0 * DCOLS + c * KC];
        #pragma unroll
        for (int i = 0; i < 2; i++) {
            int r = sr0 + i * 64;
            cpasync16(ab + r * SKB + su * 16, ga + (size_t)r * DCOLS + su * 8);
            cpasync16(bb + r * SKB + su * 16, gb + (size_t)r * DCOLS + su * 8);
        }
        asm volatile("cp.async.commit_group;" ::: "memory");
    };

    float acc[2][4][4];
    #pragma unroll
    for (int mi = 0; mi < 2; mi++)
        #pragma unroll
        for (int ni = 0; ni < 4; ni++)
            #pragma unroll
            for (int e = 0; e < 4; e++) acc[mi][ni][e] = 0.0f;

    stage(0);
    stage(1);

    #pragma unroll
    for (int c = 0; c < NCHUNK; c++) {
        if (c == NCHUNK - 1) asm volatile("cp.async.wait_group 0;" ::: "memory");
        else                 asm volatile("cp.async.wait_group 1;" ::: "memory");
        __syncthreads();   // chunk c ready; all warps done with chunk c-1

        if (c + 2 < NCHUNK) stage(c + 2);   // into slot of chunk c-1 (free)

        int slot = c % 3;
        uint32_t abase = sb + (2 * slot + 0) * TILEB + a_off;
        uint32_t bbase = sb + (2 * slot + 1) * TILEB + b_off;

        #pragma unroll
        for (int ks = 0; ks < KC / 16; ks++) {
            uint32_t a0[4], a1[4], bf0[4], bf1[4];
            ldsm4(a0, abase + ks * 32);
            ldsm4(a1, abase + 16 * SKB + ks * 32);
            ldsm4(bf0, bbase + ks * 32);
            ldsm4(bf1, bbase + 16 * SKB + ks * 32);
            mma16816(acc[0][0], a0, bf0[0], bf0[1]);
            mma16816(acc[0][1], a0, bf0[2], bf0[3]);
            mma16816(acc[1][0], a1, bf0[0], bf0[1]);
            mma16816(acc[1][1], a1, bf0[2], bf0[3]);
            mma16816(acc[0][2], a0, bf1[0], bf1[1]);
            mma16816(acc[0][3], a0, bf1[2], bf1[3]);
            mma16816(acc[1][2], a1, bf1[0], bf1[1]);
            mma16816(acc[1][3], a1, bf1[2], bf1[3]);
        }
    }

    // epilogue: exp2(min((4g-4)*log2e, 0))
    float s = 0.0f;
    #pragma unroll
    for (int mi = 0; mi < 2; mi++)
        #pragma unroll
        for (int ni = 0; ni < 4; ni++)
            #pragma unroll
            for (int e = 0; e < 4; e++) {
                float tt = fminf(acc[mi][ni][e] * C1f - C2f, 0.0f);
                s += ex2(tt);
            }
    if (bi != bj) s *= 2.0f;
    #pragma unroll
    for (int o = 16; o; o >>= 1) s += __shfl_xor_sync(0xffffffffu, s, o);
    if (lane == 0) sred[wid] = s;
    __syncthreads();
    if (tid == 0) {
        float tot = 0.f;
        #pragma unroll
        for (int i = 0; i < 16; i++) tot += sred[i];
        atomicAdd(&g_uni, tot);
        __threadfence();
        unsigned int prev = atomicAdd(&g_done, 1u);
        sflag[0] = (prev == NT - 1) ? 1 : 0;
    }
    __syncthreads();

    // last block finalizes
    if (sflag[0]) {
        float sa = 0.f;
        for (int i = tid; i < BPAIRS; i += NTHR) sa += g_align[i];
        #pragma unroll
        for (int o = 16; o; o >>= 1) sa += __shfl_xor_sync(0xffffffffu, sa, o);
        if (lane == 0) sred[wid] = sa;
        __syncthreads();
        if (tid == 0) {
            float ta = 0.f;
            #pragma unroll
            for (int i = 0; i < 16; i++) ta += sred[i];
            float align_loss = ta / (float)BPAIRS;
            float uni = *(volatile float*)&g_uni;
            float uniform_loss = (uni - (float)NROWS) / ((float)NROWS * (float)(NROWS - 1));
            out[0] = align_loss + uniform_loss;
        }
    }
}

extern "C" void kernel_launch(void* const* d_in, const int* in_sizes, int n_in,
                              void* d_out, int out_size) {
    const float* A = (const float*)d_in[0];
    const float* B = (const float*)d_in[1];
    float* out = (float*)d_out;

    cudaFuncSetAttribute(k_gram, cudaFuncAttributeMaxDynamicSharedMemorySize, SMEM_TOTAL);

    k_norm<<<BPAIRS, 256>>>(A, B);
    k_gram<<<NT, NTHR, SMEM_TOTAL>>>(out);
}